// round 15
// baseline (speedup 1.0000x reference)
#include <cuda_runtime.h>
#include <cuda_fp16.h>
#include <math.h>
#include <stdint.h>

#define B_  4
#define T_  1024
#define D_  768
#define H_  6
#define HD_ 128
#define L_  12
#define BTD (B_*T_*D_)          // 3145728
#define EPSF 1.1920929e-07f
#define BKH 32                  // k-halfs per tile (16 uint32 words)
#define NSTAGE 4

// ---------------- scratch (device globals; no allocation allowed) ----------------
__device__ float  g_x   [BTD];
__device__ float  g_x0  [BTD];
__device__ __half g_xn  [BTD];
__device__ float  g_skips[6*BTD];
__device__ float  g_ve  [3*BTD];
__device__ __half g_qkv [B_*T_*3*H_*HD_];      // [bt][which*768 + h*128 + hd]
__device__ __half g_q   [B_*H_*T_*HD_];        // [b][h][t][hd]
__device__ __half g_k   [B_*H_*T_*HD_];
__device__ __half g_vt  [B_*H_*HD_*T_];        // [b][h][hd][t]  (transposed V)
__device__ __half g_att [BTD];                 // [b][t][h*128+hd]
__device__ __half g_hbuf[B_*T_*4*D_];          // [bt][3072]
__device__ float2 g_rtab[T_*32];               // rope cos/sin table
// fp16 weight mirrors
__device__ __half g_qkvw [L_*3*H_*HD_*D_];
__device__ __half g_aprojw[L_*D_*H_*HD_];
__device__ __half g_fcw  [L_*4*D_*D_];
__device__ __half g_mprojw[L_*D_*4*D_];

// ---------------- helpers ----------------
__device__ __forceinline__ float blockReduceSum256(float v, float* red) {
    int tid = threadIdx.x;
    red[tid] = v; __syncthreads();
    for (int s = 128; s > 0; s >>= 1) {
        if (tid < s) red[tid] += red[tid + s];
        __syncthreads();
    }
    float r = red[0]; __syncthreads();
    return r;
}

__device__ __forceinline__ void mma16(float* c, const uint32_t* a, const uint32_t* b) {
    asm volatile(
        "mma.sync.aligned.m16n8k16.row.col.f32.f16.f16.f32 "
        "{%0,%1,%2,%3}, {%4,%5,%6,%7}, {%8,%9}, {%0,%1,%2,%3};"
        : "+f"(c[0]), "+f"(c[1]), "+f"(c[2]), "+f"(c[3])
        : "r"(a[0]), "r"(a[1]), "r"(a[2]), "r"(a[3]), "r"(b[0]), "r"(b[1]));
}

__device__ __forceinline__ void cp16(uint32_t saddr, const void* gptr) {
    asm volatile("cp.async.cg.shared.global [%0], [%1], 16;" :: "r"(saddr), "l"(gptr));
}

// swizzle: column-group permutation within a 16-word row
__device__ __forceinline__ int swz(int r, int cg) { return cg ^ ((r >> 1) & 3); }

__device__ __forceinline__ uint32_t packh2(float a, float b) {
    __half2 h = __floats2half2_rn(a, b);
    return *(uint32_t*)&h;
}

// ---------------- weight conversion fp32 -> fp16 (rne) ----------------
__global__ __launch_bounds__(256)
void gpt_cvtw(const float* __restrict__ src, __half* __restrict__ dst, long n)
{
    long i = ((long)blockIdx.x * 256 + threadIdx.x) * 4;
    long stride = (long)gridDim.x * 1024;
    for (; i < n; i += stride) {
        float4 v = *(const float4*)&src[i];
        __half2* d = (__half2*)&dst[i];
        d[0] = __floats2half2_rn(v.x, v.y);
        d[1] = __floats2half2_rn(v.z, v.w);
    }
}

// ---------------- rope table: cos/sin(t * freq_j), layer-invariant ----------------
__global__ __launch_bounds__(256)
void gpt_ropetab(float2* __restrict__ rtab)
{
    int i = blockIdx.x * 256 + threadIdx.x;   // t*32 + j, 32768 entries
    int t = i >> 5, j = i & 31;
    float freq = exp2f(-10.0f * (float)j / 31.0f);
    float sn, cs;
    sincosf((float)t * freq, &sn, &cs);
    rtab[i] = make_float2(cs, sn);
}

// ---------------- embedding + norm + ve gather ----------------
__global__ __launch_bounds__(256)
void gpt_embed(const int* __restrict__ seq, const float* __restrict__ ew,
               const float* __restrict__ vew,
               float* __restrict__ x, float* __restrict__ x0, float* __restrict__ ve)
{
    __shared__ float red[256];
    int bt = blockIdx.x;
    int tid = threadIdx.x;
    int idx = seq[bt];
    const float* er = ew + (long)idx * D_;
    float a0 = er[tid], a1 = er[tid + 256], a2 = er[tid + 512];
    float ss = blockReduceSum256(a0*a0 + a1*a1 + a2*a2, red);
    float r = rsqrtf(ss / (float)D_ + EPSF);
    long o = (long)bt * D_;
    x0[o + tid]       = a0 * r;  x[o + tid]       = a0 * r;
    x0[o + tid + 256] = a1 * r;  x[o + tid + 256] = a1 * r;
    x0[o + tid + 512] = a2 * r;  x[o + tid + 512] = a2 * r;
    #pragma unroll
    for (int j = 0; j < 3; j++) {
        const float* vr = vew + ((long)j * 50257 + idx) * D_;
        float* vo = ve + ((long)j * (B_*T_) + bt) * D_;
        for (int d = tid; d < D_; d += 256) vo[d] = vr[d];
    }
}

// ------- fused residual + rms norm: x = l0*(x + sw*skip) + l1*x0 ; xn = h(norm(x))
__global__ __launch_bounds__(256)
void gpt_resnorm(float* __restrict__ x, const float* __restrict__ x0,
                 const float* __restrict__ skip, const float* __restrict__ scalars,
                 int layer, __half* __restrict__ xn)
{
    __shared__ float red[256];
    float l0 = scalars[L_ + 2*layer];
    float l1 = scalars[L_ + 2*layer + 1];
    float sw = skip ? scalars[layer - 6] : 0.f;
    int tid = threadIdx.x;
    long o = (long)blockIdx.x * D_;
    float a[3];
    #pragma unroll
    for (int j = 0; j < 3; j++) {
        long i = o + tid + j*256;
        float v = x[i];
        if (skip) v += sw * skip[i];
        v = l0 * v + l1 * x0[i];
        x[i] = v;
        a[j] = v;
    }
    float ss = blockReduceSum256(a[0]*a[0] + a[1]*a[1] + a[2]*a[2], red);
    float r = rsqrtf(ss / (float)D_ + EPSF);
    #pragma unroll
    for (int j = 0; j < 3; j++)
        xn[o + tid + j*256] = __float2half_rn(a[j] * r);
}

// ---------------- rms norm (row = 768), output fp16 ----------------
__global__ __launch_bounds__(256)
void gpt_rmsnorm(const float* __restrict__ x, __half* __restrict__ y)
{
    __shared__ float red[256];
    int tid = threadIdx.x;
    const float* xr = x + (long)blockIdx.x * D_;
    float a0 = xr[tid], a1 = xr[tid + 256], a2 = xr[tid + 512];
    float ss = blockReduceSum256(a0*a0 + a1*a1 + a2*a2, red);
    float r = rsqrtf(ss / (float)D_ + EPSF);
    __half* yr = y + (long)blockIdx.x * D_;
    yr[tid]       = __float2half_rn(a0 * r);
    yr[tid + 256] = __float2half_rn(a1 * r);
    yr[tid + 512] = __float2half_rn(a2 * r);
}

// ---------------- copy (for skip buffers) ----------------
__global__ __launch_bounds__(256)
void gpt_copy(float* __restrict__ dst, const float* __restrict__ src)
{
    long i = ((long)blockIdx.x * 256 + threadIdx.x) * 4;
    float4 v = *(const float4*)&src[i];
    *(float4*)&dst[i] = v;
}

// ------- warp-level rope: one warp per (b,t,h); lane owns hd = lane + 32*j -------
__global__ __launch_bounds__(256)
void gpt_rope(const __half* __restrict__ qkv, const float* __restrict__ ve,
              const float* __restrict__ scalars, int layer,
              __half* __restrict__ q, __half* __restrict__ k, __half* __restrict__ vt,
              const float2* __restrict__ rtab)
{
    int z = blockIdx.x * 8 + (threadIdx.x >> 5);
    int lane = threadIdx.x & 31;
    int h = z % H_;
    int t = (z / H_) % T_;
    int b = z / (H_ * T_);
    long bt = (long)b * T_ + t;
    const __half* base = qkv + bt * (3*H_*HD_) + h * HD_;

    float qv[4], kv[4], vv[4];
    #pragma unroll
    for (int j = 0; j < 4; j++) {
        qv[j] = __half2float(base[lane + 32*j]);
        kv[j] = __half2float(base[H_*HD_ + lane + 32*j]);
        vv[j] = __half2float(base[2*H_*HD_ + lane + 32*j]);
    }
    float sq = qv[0]*qv[0] + qv[1]*qv[1] + qv[2]*qv[2] + qv[3]*qv[3];
    float sk = kv[0]*kv[0] + kv[1]*kv[1] + kv[2]*kv[2] + kv[3]*kv[3];
    #pragma unroll
    for (int s = 16; s > 0; s >>= 1) {
        sq += __shfl_xor_sync(0xffffffff, sq, s);
        sk += __shfl_xor_sync(0xffffffff, sk, s);
    }
    float rnq = rsqrtf(sq / (float)HD_ + EPSF);
    float rnk = rsqrtf(sk / (float)HD_ + EPSF);
    #pragma unroll
    for (int j = 0; j < 4; j++) { qv[j] *= rnq; kv[j] *= rnk; }

    float2 cs = rtab[t*32 + lane];
    float oq0 =  qv[0]*cs.x + qv[2]*cs.y;
    float oq2 = -qv[0]*cs.y + qv[2]*cs.x;
    float ok0 =  kv[0]*cs.x + kv[2]*cs.y;
    float ok2 = -kv[0]*cs.y + kv[2]*cs.x;

    long o = (((long)b * H_ + h) * T_ + t) * HD_;
    q[o + lane]      = __float2half_rn(oq0);
    q[o + lane + 32] = __float2half_rn(qv[1]);
    q[o + lane + 64] = __float2half_rn(oq2);
    q[o + lane + 96] = __float2half_rn(qv[3]);
    k[o + lane]      = __float2half_rn(ok0);
    k[o + lane + 32] = __float2half_rn(kv[1]);
    k[o + lane + 64] = __float2half_rn(ok2);
    k[o + lane + 96] = __float2half_rn(kv[3]);

    float sa0 = scalars[3*L_ + 2*layer];
    float sa1 = scalars[3*L_ + 2*layer + 1];
    long vbase = ((long)b * H_ + h) * HD_;
    #pragma unroll
    for (int j = 0; j < 4; j++) {
        float vo = sa0 * vv[j];
        if (ve) vo += sa1 * ve[bt * D_ + h * HD_ + lane + 32*j];
        vt[(vbase + lane + 32*j) * T_ + t] = __float2half_rn(vo);
    }
}

// =================================================================================
// Fused flash attention: 128 q-rows per CTA (8 warps), K/V tiles of 64, online
// softmax, double-buffered cp.async K/V. Q/K: [b][h][t][hd]; V: [b][h][hd][t].
// =================================================================================
__global__ void __launch_bounds__(256, 1)
gpt_flash(const __half* __restrict__ Q, const __half* __restrict__ K,
          const __half* __restrict__ Vt, __half* __restrict__ att)
{
    const int qt = 7 - blockIdx.x;            // heavy tiles first
    const int bh = blockIdx.y;
    const int b = bh / H_, h = bh % H_;
    const int tid = threadIdx.x;
    const int w = tid >> 5, lane = tid & 31;
    const int g = lane >> 2, t = lane & 3;

    const __half* Qb = Q  + (((long)bh * T_) + qt*128) * HD_;
    const __half* Kb = K  + (long)bh * T_ * HD_;
    const __half* Vb = Vt + (long)bh * HD_ * T_;

    extern __shared__ uint32_t sm[];
    uint32_t sbase = (uint32_t)__cvta_generic_to_shared(sm);

    #pragma unroll
    for (int j = 0; j < 8; j++) {
        int i = tid + j*256;
        int row = i >> 4, c16 = i & 15;
        int kc = c16 >> 2, wg = c16 & 3;
        uint32_t word = (kc*128 + row)*16 + swz(row, wg)*4;
        cp16(sbase + 4u*word, Qb + row*HD_ + c16*8);
    }
    asm volatile("cp.async.commit_group;" ::: "memory");

    const int NT = 2*qt + 2;

    auto issueKV = [&](int kt) {
        int s = kt & 1;
        uint32_t kw0 = 8192 + s*8192;
        #pragma unroll
        for (int j = 0; j < 4; j++) {
            int i = tid + j*256;
            int row = i >> 4, c16 = i & 15;
            int kc = c16 >> 2, wg = c16 & 3;
            uint32_t word = kw0 + (kc*64 + row)*16 + swz(row, wg)*4;
            cp16(sbase + 4u*word, Kb + (long)(kt*64 + row)*HD_ + c16*8);
        }
        uint32_t vw0 = 12288 + s*8192;
        #pragma unroll
        for (int j = 0; j < 4; j++) {
            int i = tid + j*256;
            int row = i >> 3, c16 = i & 7;
            int kc = c16 >> 2, wg = c16 & 3;
            uint32_t word = vw0 + (kc*128 + row)*16 + swz(row, wg)*4;
            cp16(sbase + 4u*word, Vb + (long)row*T_ + kt*64 + c16*8);
        }
        asm volatile("cp.async.commit_group;" ::: "memory");
    };

    issueKV(0); issueKV(1);

    float m0 = -1e30f, m1 = -1e30f, l0 = 0.f, l1 = 0.f;
    float oacc[16][4];
    #pragma unroll
    for (int a = 0; a < 16; a++)
        #pragma unroll
        for (int c = 0; c < 4; c++) oacc[a][c] = 0.f;

    const int r0 = w*16 + g;
    const int grow = qt*128 + r0;

    for (int kt = 0; kt < NT; kt++) {
        if (kt + 1 < NT) asm volatile("cp.async.wait_group 1;" ::: "memory");
        else             asm volatile("cp.async.wait_group 0;" ::: "memory");
        __syncthreads();

        const uint32_t* Kc = sm + 8192 + (kt & 1)*8192;
        const uint32_t* Vc = sm + 12288 + (kt & 1)*8192;

        float sacc[8][4];
        #pragma unroll
        for (int a = 0; a < 8; a++)
            #pragma unroll
            for (int c = 0; c < 4; c++) sacc[a][c] = 0.f;

        #pragma unroll
        for (int kc = 0; kc < 4; kc++) {
            const uint32_t* Qc = sm + kc*2048;
            const uint32_t* Kk = Kc + kc*1024;
            #pragma unroll
            for (int ks = 0; ks < 2; ks++) {
                int s0 = swz(r0, ks*2)*4 + t;
                int s1 = swz(r0, ks*2 + 1)*4 + t;
                uint32_t af[4];
                af[0] = Qc[r0*16 + s0];
                af[1] = Qc[(r0+8)*16 + s0];
                af[2] = Qc[r0*16 + s1];
                af[3] = Qc[(r0+8)*16 + s1];
                #pragma unroll
                for (int ni = 0; ni < 8; ni++) {
                    int nr = ni*8 + g;
                    uint32_t bf[2];
                    bf[0] = Kk[nr*16 + swz(nr, ks*2)*4 + t];
                    bf[1] = Kk[nr*16 + swz(nr, ks*2 + 1)*4 + t];
                    mma16(sacc[ni], af, bf);
                }
            }
        }

        bool diag = (kt >= 2*qt);
        #pragma unroll
        for (int ni = 0; ni < 8; ni++) {
            int col = kt*64 + ni*8 + t*2;
            float v0 = 0.12f * sacc[ni][0];
            float v1 = 0.12f * sacc[ni][1];
            float v2 = 0.12f * sacc[ni][2];
            float v3 = 0.12f * sacc[ni][3];
            if (diag) {
                if (col     > grow)     v0 = -1e30f;
                if (col + 1 > grow)     v1 = -1e30f;
                if (col     > grow + 8) v2 = -1e30f;
                if (col + 1 > grow + 8) v3 = -1e30f;
            }
            sacc[ni][0] = v0; sacc[ni][1] = v1; sacc[ni][2] = v2; sacc[ni][3] = v3;
        }

        float rm0 = -1e30f, rm1 = -1e30f;
        #pragma unroll
        for (int ni = 0; ni < 8; ni++) {
            rm0 = fmaxf(rm0, fmaxf(sacc[ni][0], sacc[ni][1]));
            rm1 = fmaxf(rm1, fmaxf(sacc[ni][2], sacc[ni][3]));
        }
        rm0 = fmaxf(rm0, __shfl_xor_sync(0xffffffff, rm0, 1));
        rm0 = fmaxf(rm0, __shfl_xor_sync(0xffffffff, rm0, 2));
        rm1 = fmaxf(rm1, __shfl_xor_sync(0xffffffff, rm1, 1));
        rm1 = fmaxf(rm1, __shfl_xor_sync(0xffffffff, rm1, 2));

        float mn0 = fmaxf(m0, rm0), mn1 = fmaxf(m1, rm1);
        float sc0 = __expf(m0 - mn0), sc1 = __expf(m1 - mn1);
        m0 = mn0; m1 = mn1;

        float ls0 = 0.f, ls1 = 0.f;
        uint32_t phg[8], phg8[8];
        #pragma unroll
        for (int ni = 0; ni < 8; ni++) {
            float p0 = __expf(sacc[ni][0] - mn0);
            float p1 = __expf(sacc[ni][1] - mn0);
            float p2 = __expf(sacc[ni][2] - mn1);
            float p3 = __expf(sacc[ni][3] - mn1);
            ls0 += p0 + p1; ls1 += p2 + p3;
            phg[ni]  = packh2(p0, p1);
            phg8[ni] = packh2(p2, p3);
        }
        ls0 += __shfl_xor_sync(0xffffffff, ls0, 1);
        ls0 += __shfl_xor_sync(0xffffffff, ls0, 2);
        ls1 += __shfl_xor_sync(0xffffffff, ls1, 1);
        ls1 += __shfl_xor_sync(0xffffffff, ls1, 2);
        l0 = l0*sc0 + ls0;
        l1 = l1*sc1 + ls1;

        #pragma unroll
        for (int ni = 0; ni < 16; ni++) {
            oacc[ni][0] *= sc0; oacc[ni][1] *= sc0;
            oacc[ni][2] *= sc1; oacc[ni][3] *= sc1;
        }

        #pragma unroll
        for (int kk = 0; kk < 4; kk++) {
            uint32_t af[4] = { phg[2*kk], phg8[2*kk], phg[2*kk+1], phg8[2*kk+1] };
            const uint32_t* Vk = Vc + (kk >> 1)*2048;
            int ks = kk & 1;
            #pragma unroll
            for (int ni = 0; ni < 16; ni++) {
                int nr = ni*8 + g;
                uint32_t bf[2];
                bf[0] = Vk[nr*16 + swz(nr, ks*2)*4 + t];
                bf[1] = Vk[nr*16 + swz(nr, ks*2 + 1)*4 + t];
                mma16(oacc[ni], af, bf);
            }
        }

        __syncthreads();
        if (kt + 2 < NT) issueKV(kt + 2);
    }

    float inv0 = 1.f / l0, inv1 = 1.f / l1;
    long base0 = ((long)b*T_ + grow) * D_ + h*HD_;
    long base1 = base0 + 8L*D_;
    #pragma unroll
    for (int ni = 0; ni < 16; ni++) {
        int col = ni*8 + t*2;
        *(uint32_t*)&att[base0 + col] = packh2(oacc[ni][0]*inv0, oacc[ni][1]*inv0);
        *(uint32_t*)&att[base1 + col] = packh2(oacc[ni][2]*inv1, oacc[ni][3]*inv1);
    }
}

// =================================================================================
// fp16 tensor-core GEMM (m16n8k16, fp32 accum), cp.async 4-stage pipeline.
// EPI: 0=store half, 1=accumulate into float C, 2=relu^2 store half,
//      5=split-K atomicAdd into float C (blockIdx.z = K-split; aZ/bZ = col offset)
// =================================================================================
template<int EPI, int MT>
__global__ void
__launch_bounds__(MT == 4 ? 512 : 256, MT == 4 ? 1 : 2)
gpt_gemm(const __half* __restrict__ A, const __half* __restrict__ Bm, void* __restrict__ Cv,
         float* __restrict__ C2,
         int K, int lda, int ldb, int ldc,
         long aZ, long bZ, int zdiv, long c1, long c2, float alpha, int ktri)
{
    constexpr int THREADS = (MT == 4) ? 512 : 256;
    constexpr int BM = MT * 64;
    constexpr int AROWS = THREADS / 4;
    constexpr int APASS = BM / AROWS;
    constexpr int BPASS = 128 / AROWS;

    const int m0 = blockIdx.y * BM, n0 = blockIdx.x * 128;

    int z = blockIdx.z;
    A  += (long)z * aZ;
    Bm += (long)z * bZ;
    long coff = (long)(z / zdiv) * c1 + (long)(z % zdiv) * c2;
    float*  Cf = (float*)Cv + coff;
    __half* Ch = (__half*)Cv + coff;

    const int tid  = threadIdx.x;
    const int lane = tid & 31, warp = tid >> 5;
    const int wm = warp >> 2, wn = warp & 3;
    const int g = lane >> 2, t = lane & 3;

    extern __shared__ uint32_t smem[];
    uint32_t* As = smem;
    uint32_t* Bs = smem + NSTAGE * BM * 16;
    uint32_t as0 = (uint32_t)__cvta_generic_to_shared(As);
    uint32_t bs0 = (uint32_t)__cvta_generic_to_shared(Bs);

    int keff = K;
    if (ktri) { int kk = m0 + BM; keff = kk < K ? kk : K; }
    const int NT = keff / BKH;

    float acc[4][4][4];
    #pragma unroll
    for (int a = 0; a < 4; a++)
        #pragma unroll
        for (int b = 0; b < 4; b++)
            #pragma unroll
            for (int c = 0; c < 4; c++) acc[a][b][c] = 0.f;

    const int ar  = tid >> 2;
    const int acg = tid & 3;
    const __half* apB = A  + (long)(m0 + ar) * lda + acg*8;
    const __half* bpB = Bm + (long)(n0 + ar) * ldb + acg*8;

    auto issue = [&](int kt) {
        int s = kt % NSTAGE;
        const __half* ap = apB + kt*BKH;
        #pragma unroll
        for (int j = 0; j < APASS; j++) {
            int r = ar + AROWS*j;
            cp16(as0 + 4u*(s*BM*16 + r*16 + swz(r, acg)*4), ap + (long)(AROWS*j) * lda);
        }
        const __half* bp = bpB + kt*BKH;
        #pragma unroll
        for (int j = 0; j < BPASS; j++) {
            int r = ar + AROWS*j;
            cp16(bs0 + 4u*(s*128*16 + r*16 + swz(r, acg)*4), bp + (long)(AROWS*j) * ldb);
        }
        asm volatile("cp.async.commit_group;" ::: "memory");
    };

    issue(0); issue(1); issue(2);

    for (int kt = 0; kt < NT; kt++) {
        if (kt + 1 >= NT)      asm volatile("cp.async.wait_group 0;" ::: "memory");
        else if (kt + 2 >= NT) asm volatile("cp.async.wait_group 1;" ::: "memory");
        else                   asm volatile("cp.async.wait_group 2;" ::: "memory");
        __syncthreads();

        const uint32_t* Ab = As + (kt % NSTAGE) * BM * 16;
        const uint32_t* Bb = Bs + (kt % NSTAGE) * 128 * 16;
        #pragma unroll
        for (int ks = 0; ks < 2; ks++) {
            uint32_t af[4][4];
            #pragma unroll
            for (int mi = 0; mi < 4; mi++) {
                int r0 = wm*64 + mi*16 + g;
                int s0 = swz(r0, ks*2)*4 + t;
                int s1 = swz(r0, ks*2 + 1)*4 + t;
                af[mi][0] = Ab[r0*16 + s0];
                af[mi][1] = Ab[(r0+8)*16 + s0];
                af[mi][2] = Ab[r0*16 + s1];
                af[mi][3] = Ab[(r0+8)*16 + s1];
            }
            uint32_t bf[4][2];
            #pragma unroll
            for (int ni = 0; ni < 4; ni++) {
                int nr = wn*32 + ni*8 + g;
                bf[ni][0] = Bb[nr*16 + swz(nr, ks*2)*4 + t];
                bf[ni][1] = Bb[nr*16 + swz(nr, ks*2 + 1)*4 + t];
            }
            #pragma unroll
            for (int mi = 0; mi < 4; mi++)
                #pragma unroll
                for (int ni = 0; ni < 4; ni++)
                    mma16(acc[mi][ni], af[mi], bf[ni]);
        }

        if (kt + NSTAGE - 1 < NT) issue(kt + NSTAGE - 1);
    }

    // ---- epilogue ----
    #pragma unroll
    for (int mi = 0; mi < 4; mi++) {
        int row = m0 + wm*64 + mi*16 + g;
        #pragma unroll
        for (int ni = 0; ni < 4; ni++) {
            int col = n0 + wn*32 + ni*8 + t*2;
            float* a4 = acc[mi][ni];
            #pragma unroll
            for (int half_ = 0; half_ < 2; half_++) {
                int r = row + half_ * 8;
                float c0 = a4[half_*2 + 0], c1 = a4[half_*2 + 1];
                if (EPI == 0) {
                    *(__half2*)&Ch[(long)r * ldc + col] = __floats2half2_rn(c0, c1);
                } else if (EPI == 2) {
                    float r0 = fmaxf(c0, 0.f), r1 = fmaxf(c1, 0.f);
                    *(__half2*)&Ch[(long)r * ldc + col] = __floats2half2_rn(r0*r0, r1*r1);
                } else if (EPI == 5) {
                    atomicAdd(&Cf[(long)r * ldc + col],     c0);
                    atomicAdd(&Cf[(long)r * ldc + col + 1], c1);
                } else {  // EPI == 1
                    float* cp = &Cf[(long)r * ldc + col];
                    float2 o = *(float2*)cp;
                    *(float2*)cp = make_float2(o.x + c0, o.y + c1);
                }
            }
        }
    }
}

// ---------------- final norm -> output ----------------
__global__ __launch_bounds__(256)
void gpt_finalnorm(const float* __restrict__ x, float* __restrict__ out)
{
    __shared__ float red[256];
    int tid = threadIdx.x;
    const float* xr = x + (long)blockIdx.x * D_;
    float a0 = xr[tid], a1 = xr[tid + 256], a2 = xr[tid + 512];
    float ss = blockReduceSum256(a0*a0 + a1*a1 + a2*a2, red);
    float r = rsqrtf(ss / (float)D_ + EPSF);
    float* yr = out + (long)blockIdx.x * D_;
    yr[tid] = a0 * r; yr[tid + 256] = a1 * r; yr[tid + 512] = a2 * r;
}

// ---------------- host orchestration ----------------
#define SMEM4 (NSTAGE * (256 + 128) * 16 * 4)   // 98304
#define SMEM2 (NSTAGE * (128 + 128) * 16 * 4)   // 65536
#define SMEMF ((8192 + 2*8192) * 4)             // 98304 (flash)

extern "C" void kernel_launch(void* const* d_in, const int* in_sizes, int n_in,
                              void* d_out, int out_size)
{
    const int*   seq         = (const int*)  d_in[0];
    const float* embed_w     = (const float*)d_in[1];
    const float* ve_w        = (const float*)d_in[2];
    const float* qkv_w       = (const float*)d_in[3];
    const float* attn_proj_w = (const float*)d_in[4];
    const float* mlp_fc_w    = (const float*)d_in[5];
    const float* mlp_proj_w  = (const float*)d_in[6];
    const float* scalars     = (const float*)d_in[7];

    cudaFuncSetAttribute(gpt_gemm<0,4>, cudaFuncAttributeMaxDynamicSharedMemorySize, SMEM4);
    cudaFuncSetAttribute(gpt_gemm<2,4>, cudaFuncAttributeMaxDynamicSharedMemorySize, SMEM4);
    cudaFuncSetAttribute(gpt_gemm<5,2>, cudaFuncAttributeMaxDynamicSharedMemorySize, SMEM2);
    cudaFuncSetAttribute(gpt_flash,     cudaFuncAttributeMaxDynamicSharedMemorySize, SMEMF);

    float *x, *x0, *skips, *ve;
    float2 *rtab;
    __half *xn, *qkv, *q, *k, *vt, *att, *hbuf;
    __half *qkvw, *aprojw, *fcw, *mprojw;
    cudaGetSymbolAddress((void**)&x,      g_x);
    cudaGetSymbolAddress((void**)&x0,     g_x0);
    cudaGetSymbolAddress((void**)&xn,     g_xn);
    cudaGetSymbolAddress((void**)&skips,  g_skips);
    cudaGetSymbolAddress((void**)&ve,     g_ve);
    cudaGetSymbolAddress((void**)&qkv,    g_qkv);
    cudaGetSymbolAddress((void**)&q,      g_q);
    cudaGetSymbolAddress((void**)&k,      g_k);
    cudaGetSymbolAddress((void**)&vt,     g_vt);
    cudaGetSymbolAddress((void**)&att,    g_att);
    cudaGetSymbolAddress((void**)&hbuf,   g_hbuf);
    cudaGetSymbolAddress((void**)&rtab,   g_rtab);
    cudaGetSymbolAddress((void**)&qkvw,   g_qkvw);
    cudaGetSymbolAddress((void**)&aprojw, g_aprojw);
    cudaGetSymbolAddress((void**)&fcw,    g_fcw);
    cudaGetSymbolAddress((void**)&mprojw, g_mprojw);

    const int NTOK = B_ * T_;   // 4096

    gpt_cvtw<<<2048, 256>>>(qkv_w,       qkvw,   (long)L_*3*H_*HD_*D_);
    gpt_cvtw<<<2048, 256>>>(attn_proj_w, aprojw, (long)L_*D_*H_*HD_);
    gpt_cvtw<<<2048, 256>>>(mlp_fc_w,    fcw,    (long)L_*4*D_*D_);
    gpt_cvtw<<<2048, 256>>>(mlp_proj_w,  mprojw, (long)L_*D_*4*D_);
    gpt_ropetab<<<128, 256>>>(rtab);

    gpt_embed<<<NTOK, 256>>>(seq, embed_w, ve_w, x, x0, ve);

    for (int i = 0; i < L_; i++) {
        const float* skip = (i >= 6) ? (skips + (long)(11 - i) * BTD) : nullptr;
        gpt_resnorm<<<NTOK, 256>>>(x, x0, skip, scalars, i, xn);

        if (i != 7) {
            // qkv = xn @ W_qkv^T : [4096,768] x [2304,768]^T  -> half
            gpt_gemm<0,4><<<dim3(18, 16, 1), 512, SMEM4>>>(
                xn, qkvw + (long)i * 3 * H_ * HD_ * D_, qkv, nullptr,
                D_, D_, D_, 3*H_*HD_, 0, 0, 1, 0, 0, 1.f, 0);

            const float* vep = nullptr;
            if (i < 3)       vep = ve + (long)i * BTD;
            else if (i >= 9) vep = ve + (long)(i - 9) * BTD;
            gpt_rope<<<B_*T_*H_/8, 256>>>(qkv, vep, scalars, i, q, k, vt, rtab);

            // fused flash attention -> att (half)
            gpt_flash<<<dim3(8, B_*H_), 256, SMEMF>>>(q, k, vt, att);

            // x += att @ W_proj^T  (split-K=2, atomicAdd)
            gpt_gemm<5,2><<<dim3(6, 32, 2), 256, SMEM2>>>(
                att, aprojw + (long)i * D_ * H_ * HD_, x, nullptr,
                (H_*HD_)/2, H_*HD_, H_*HD_, D_,
                (H_*HD_)/2, (H_*HD_)/2, 1, 0, 0, 1.f, 0);

            gpt_rmsnorm<<<NTOK, 256>>>(x, xn);
        }

        // h = relu(xn @ W_fc^T)^2 : [4096,768] x [3072,768]^T -> half
        gpt_gemm<2,4><<<dim3(24, 16, 1), 512, SMEM4>>>(
            xn, fcw + (long)i * 4 * D_ * D_, hbuf, nullptr,
            D_, D_, D_, 4*D_, 0, 0, 1, 0, 0, 1.f, 0);

        // x += h @ W_proj^T  (split-K=2, atomicAdd)
        gpt_gemm<5,2><<<dim3(6, 32, 2), 256, SMEM2>>>(
            hbuf, mprojw + (long)i * D_ * 4 * D_, x, nullptr,
            (4*D_)/2, 4*D_, 4*D_, D_,
            (4*D_)/2, (4*D_)/2, 1, 0, 0, 1.f, 0);

        if (i < 6) gpt_copy<<<BTD/1024, 256>>>(skips + (long)i * BTD, x);
    }

    gpt_finalnorm<<<NTOK, 256>>>(x, (float*)d_out);
}

// round 16
// speedup vs baseline: 1.0027x; 1.0027x over previous
#include <cuda_runtime.h>
#include <cuda_fp16.h>
#include <math.h>
#include <stdint.h>

#define B_  4
#define T_  1024
#define D_  768
#define H_  6
#define HD_ 128
#define L_  12
#define BTD (B_*T_*D_)          // 3145728
#define EPSF 1.1920929e-07f
#define BKH 32                  // k-halfs per tile (16 uint32 words)
#define NSTAGE 4

// ---------------- scratch (device globals; no allocation allowed) ----------------
__device__ float  g_x   [BTD];
__device__ float  g_x0  [BTD];
__device__ __half g_xn  [BTD];
__device__ float  g_skips[6*BTD];
__device__ float  g_ve  [3*BTD];
__device__ __half g_qkv [B_*T_*3*H_*HD_];      // [bt][which*768 + h*128 + hd]
__device__ __half g_q   [B_*H_*T_*HD_];        // [b][h][t][hd]
__device__ __half g_k   [B_*H_*T_*HD_];
__device__ __half g_vt  [B_*H_*HD_*T_];        // [b][h][hd][t]  (transposed V)
__device__ __half g_att [BTD];                 // [b][t][h*128+hd]
__device__ __half g_hbuf[B_*T_*4*D_];          // [bt][3072]
__device__ float2 g_rtab[T_*32];               // rope cos/sin table
// fp16 weight mirrors
__device__ __half g_qkvw [L_*3*H_*HD_*D_];
__device__ __half g_aprojw[L_*D_*H_*HD_];
__device__ __half g_fcw  [L_*4*D_*D_];
__device__ __half g_mprojw[L_*D_*4*D_];

// ---------------- helpers ----------------
__device__ __forceinline__ float blockReduceSum256(float v, float* red) {
    int tid = threadIdx.x;
    red[tid] = v; __syncthreads();
    for (int s = 128; s > 0; s >>= 1) {
        if (tid < s) red[tid] += red[tid + s];
        __syncthreads();
    }
    float r = red[0]; __syncthreads();
    return r;
}

__device__ __forceinline__ void mma16(float* c, const uint32_t* a, const uint32_t* b) {
    asm volatile(
        "mma.sync.aligned.m16n8k16.row.col.f32.f16.f16.f32 "
        "{%0,%1,%2,%3}, {%4,%5,%6,%7}, {%8,%9}, {%0,%1,%2,%3};"
        : "+f"(c[0]), "+f"(c[1]), "+f"(c[2]), "+f"(c[3])
        : "r"(a[0]), "r"(a[1]), "r"(a[2]), "r"(a[3]), "r"(b[0]), "r"(b[1]));
}

__device__ __forceinline__ void cp16(uint32_t saddr, const void* gptr) {
    asm volatile("cp.async.cg.shared.global [%0], [%1], 16;" :: "r"(saddr), "l"(gptr));
}

// swizzle: column-group permutation within a 16-word row
__device__ __forceinline__ int swz(int r, int cg) { return cg ^ ((r >> 1) & 3); }

__device__ __forceinline__ uint32_t packh2(float a, float b) {
    __half2 h = __floats2half2_rn(a, b);
    return *(uint32_t*)&h;
}

// ---------------- weight conversion fp32 -> fp16 (rne) ----------------
__global__ __launch_bounds__(256)
void gpt_cvtw(const float* __restrict__ src, __half* __restrict__ dst, long n)
{
    long i = ((long)blockIdx.x * 256 + threadIdx.x) * 4;
    long stride = (long)gridDim.x * 1024;
    for (; i < n; i += stride) {
        float4 v = *(const float4*)&src[i];
        __half2* d = (__half2*)&dst[i];
        d[0] = __floats2half2_rn(v.x, v.y);
        d[1] = __floats2half2_rn(v.z, v.w);
    }
}

// ---------------- rope table: cos/sin(t * freq_j), layer-invariant ----------------
__global__ __launch_bounds__(256)
void gpt_ropetab(float2* __restrict__ rtab)
{
    int i = blockIdx.x * 256 + threadIdx.x;   // t*32 + j, 32768 entries
    int t = i >> 5, j = i & 31;
    float freq = exp2f(-10.0f * (float)j / 31.0f);
    float sn, cs;
    sincosf((float)t * freq, &sn, &cs);
    rtab[i] = make_float2(cs, sn);
}

// ---------------- embedding + norm + ve gather ----------------
__global__ __launch_bounds__(256)
void gpt_embed(const int* __restrict__ seq, const float* __restrict__ ew,
               const float* __restrict__ vew,
               float* __restrict__ x, float* __restrict__ x0, float* __restrict__ ve)
{
    __shared__ float red[256];
    int bt = blockIdx.x;
    int tid = threadIdx.x;
    int idx = seq[bt];
    const float* er = ew + (long)idx * D_;
    float a0 = er[tid], a1 = er[tid + 256], a2 = er[tid + 512];
    float ss = blockReduceSum256(a0*a0 + a1*a1 + a2*a2, red);
    float r = rsqrtf(ss / (float)D_ + EPSF);
    long o = (long)bt * D_;
    x0[o + tid]       = a0 * r;  x[o + tid]       = a0 * r;
    x0[o + tid + 256] = a1 * r;  x[o + tid + 256] = a1 * r;
    x0[o + tid + 512] = a2 * r;  x[o + tid + 512] = a2 * r;
    #pragma unroll
    for (int j = 0; j < 3; j++) {
        const float* vr = vew + ((long)j * 50257 + idx) * D_;
        float* vo = ve + ((long)j * (B_*T_) + bt) * D_;
        for (int d = tid; d < D_; d += 256) vo[d] = vr[d];
    }
}

// ------- fused residual + rms norm: x = l0*(x + sw*skip) + l1*x0 ; xn = h(norm(x))
__global__ __launch_bounds__(256)
void gpt_resnorm(float* __restrict__ x, const float* __restrict__ x0,
                 const float* __restrict__ skip, const float* __restrict__ scalars,
                 int layer, __half* __restrict__ xn)
{
    __shared__ float red[256];
    float l0 = scalars[L_ + 2*layer];
    float l1 = scalars[L_ + 2*layer + 1];
    float sw = skip ? scalars[layer - 6] : 0.f;
    int tid = threadIdx.x;
    long o = (long)blockIdx.x * D_;
    float a[3];
    #pragma unroll
    for (int j = 0; j < 3; j++) {
        long i = o + tid + j*256;
        float v = x[i];
        if (skip) v += sw * skip[i];
        v = l0 * v + l1 * x0[i];
        x[i] = v;
        a[j] = v;
    }
    float ss = blockReduceSum256(a[0]*a[0] + a[1]*a[1] + a[2]*a[2], red);
    float r = rsqrtf(ss / (float)D_ + EPSF);
    #pragma unroll
    for (int j = 0; j < 3; j++)
        xn[o + tid + j*256] = __float2half_rn(a[j] * r);
}

// ---------------- rms norm (row = 768), output fp16 ----------------
__global__ __launch_bounds__(256)
void gpt_rmsnorm(const float* __restrict__ x, __half* __restrict__ y)
{
    __shared__ float red[256];
    int tid = threadIdx.x;
    const float* xr = x + (long)blockIdx.x * D_;
    float a0 = xr[tid], a1 = xr[tid + 256], a2 = xr[tid + 512];
    float ss = blockReduceSum256(a0*a0 + a1*a1 + a2*a2, red);
    float r = rsqrtf(ss / (float)D_ + EPSF);
    __half* yr = y + (long)blockIdx.x * D_;
    yr[tid]       = __float2half_rn(a0 * r);
    yr[tid + 256] = __float2half_rn(a1 * r);
    yr[tid + 512] = __float2half_rn(a2 * r);
}

// ---------------- copy (for skip buffers) ----------------
__global__ __launch_bounds__(256)
void gpt_copy(float* __restrict__ dst, const float* __restrict__ src)
{
    long i = ((long)blockIdx.x * 256 + threadIdx.x) * 4;
    float4 v = *(const float4*)&src[i];
    *(float4*)&dst[i] = v;
}

// ------- warp-level rope: one warp per (b,t,h); lane owns hd = lane + 32*j -------
__global__ __launch_bounds__(256)
void gpt_rope(const __half* __restrict__ qkv, const float* __restrict__ ve,
              const float* __restrict__ scalars, int layer,
              __half* __restrict__ q, __half* __restrict__ k, __half* __restrict__ vt,
              const float2* __restrict__ rtab)
{
    int z = blockIdx.x * 8 + (threadIdx.x >> 5);
    int lane = threadIdx.x & 31;
    int h = z % H_;
    int t = (z / H_) % T_;
    int b = z / (H_ * T_);
    long bt = (long)b * T_ + t;
    const __half* base = qkv + bt * (3*H_*HD_) + h * HD_;

    float qv[4], kv[4], vv[4];
    #pragma unroll
    for (int j = 0; j < 4; j++) {
        qv[j] = __half2float(base[lane + 32*j]);
        kv[j] = __half2float(base[H_*HD_ + lane + 32*j]);
        vv[j] = __half2float(base[2*H_*HD_ + lane + 32*j]);
    }
    float sq = qv[0]*qv[0] + qv[1]*qv[1] + qv[2]*qv[2] + qv[3]*qv[3];
    float sk = kv[0]*kv[0] + kv[1]*kv[1] + kv[2]*kv[2] + kv[3]*kv[3];
    #pragma unroll
    for (int s = 16; s > 0; s >>= 1) {
        sq += __shfl_xor_sync(0xffffffff, sq, s);
        sk += __shfl_xor_sync(0xffffffff, sk, s);
    }
    float rnq = rsqrtf(sq / (float)HD_ + EPSF);
    float rnk = rsqrtf(sk / (float)HD_ + EPSF);
    #pragma unroll
    for (int j = 0; j < 4; j++) { qv[j] *= rnq; kv[j] *= rnk; }

    float2 cs = rtab[t*32 + lane];
    float oq0 =  qv[0]*cs.x + qv[2]*cs.y;
    float oq2 = -qv[0]*cs.y + qv[2]*cs.x;
    float ok0 =  kv[0]*cs.x + kv[2]*cs.y;
    float ok2 = -kv[0]*cs.y + kv[2]*cs.x;

    long o = (((long)b * H_ + h) * T_ + t) * HD_;
    q[o + lane]      = __float2half_rn(oq0);
    q[o + lane + 32] = __float2half_rn(qv[1]);
    q[o + lane + 64] = __float2half_rn(oq2);
    q[o + lane + 96] = __float2half_rn(qv[3]);
    k[o + lane]      = __float2half_rn(ok0);
    k[o + lane + 32] = __float2half_rn(kv[1]);
    k[o + lane + 64] = __float2half_rn(ok2);
    k[o + lane + 96] = __float2half_rn(kv[3]);

    float sa0 = scalars[3*L_ + 2*layer];
    float sa1 = scalars[3*L_ + 2*layer + 1];
    long vbase = ((long)b * H_ + h) * HD_;
    #pragma unroll
    for (int j = 0; j < 4; j++) {
        float vo = sa0 * vv[j];
        if (ve) vo += sa1 * ve[bt * D_ + h * HD_ + lane + 32*j];
        vt[(vbase + lane + 32*j) * T_ + t] = __float2half_rn(vo);
    }
}

// =================================================================================
// Fused flash attention: 128 q-rows per CTA (8 warps), K/V tiles of 64, online
// softmax, double-buffered cp.async K/V. Q/K: [b][h][t][hd]; V: [b][h][hd][t].
// =================================================================================
__global__ void __launch_bounds__(256, 1)
gpt_flash(const __half* __restrict__ Q, const __half* __restrict__ K,
          const __half* __restrict__ Vt, __half* __restrict__ att)
{
    const int qt = 7 - blockIdx.x;            // heavy tiles first
    const int bh = blockIdx.y;
    const int b = bh / H_, h = bh % H_;
    const int tid = threadIdx.x;
    const int w = tid >> 5, lane = tid & 31;
    const int g = lane >> 2, t = lane & 3;

    const __half* Qb = Q  + (((long)bh * T_) + qt*128) * HD_;
    const __half* Kb = K  + (long)bh * T_ * HD_;
    const __half* Vb = Vt + (long)bh * HD_ * T_;

    extern __shared__ uint32_t sm[];
    uint32_t sbase = (uint32_t)__cvta_generic_to_shared(sm);

    #pragma unroll
    for (int j = 0; j < 8; j++) {
        int i = tid + j*256;
        int row = i >> 4, c16 = i & 15;
        int kc = c16 >> 2, wg = c16 & 3;
        uint32_t word = (kc*128 + row)*16 + swz(row, wg)*4;
        cp16(sbase + 4u*word, Qb + row*HD_ + c16*8);
    }
    asm volatile("cp.async.commit_group;" ::: "memory");

    const int NT = 2*qt + 2;

    auto issueKV = [&](int kt) {
        int s = kt & 1;
        uint32_t kw0 = 8192 + s*8192;
        #pragma unroll
        for (int j = 0; j < 4; j++) {
            int i = tid + j*256;
            int row = i >> 4, c16 = i & 15;
            int kc = c16 >> 2, wg = c16 & 3;
            uint32_t word = kw0 + (kc*64 + row)*16 + swz(row, wg)*4;
            cp16(sbase + 4u*word, Kb + (long)(kt*64 + row)*HD_ + c16*8);
        }
        uint32_t vw0 = 12288 + s*8192;
        #pragma unroll
        for (int j = 0; j < 4; j++) {
            int i = tid + j*256;
            int row = i >> 3, c16 = i & 7;
            int kc = c16 >> 2, wg = c16 & 3;
            uint32_t word = vw0 + (kc*128 + row)*16 + swz(row, wg)*4;
            cp16(sbase + 4u*word, Vb + (long)row*T_ + kt*64 + c16*8);
        }
        asm volatile("cp.async.commit_group;" ::: "memory");
    };

    issueKV(0); issueKV(1);

    float m0 = -1e30f, m1 = -1e30f, l0 = 0.f, l1 = 0.f;
    float oacc[16][4];
    #pragma unroll
    for (int a = 0; a < 16; a++)
        #pragma unroll
        for (int c = 0; c < 4; c++) oacc[a][c] = 0.f;

    const int r0 = w*16 + g;
    const int grow = qt*128 + r0;

    for (int kt = 0; kt < NT; kt++) {
        if (kt + 1 < NT) asm volatile("cp.async.wait_group 1;" ::: "memory");
        else             asm volatile("cp.async.wait_group 0;" ::: "memory");
        __syncthreads();

        const uint32_t* Kc = sm + 8192 + (kt & 1)*8192;
        const uint32_t* Vc = sm + 12288 + (kt & 1)*8192;

        float sacc[8][4];
        #pragma unroll
        for (int a = 0; a < 8; a++)
            #pragma unroll
            for (int c = 0; c < 4; c++) sacc[a][c] = 0.f;

        #pragma unroll
        for (int kc = 0; kc < 4; kc++) {
            const uint32_t* Qc = sm + kc*2048;
            const uint32_t* Kk = Kc + kc*1024;
            #pragma unroll
            for (int ks = 0; ks < 2; ks++) {
                int s0 = swz(r0, ks*2)*4 + t;
                int s1 = swz(r0, ks*2 + 1)*4 + t;
                uint32_t af[4];
                af[0] = Qc[r0*16 + s0];
                af[1] = Qc[(r0+8)*16 + s0];
                af[2] = Qc[r0*16 + s1];
                af[3] = Qc[(r0+8)*16 + s1];
                #pragma unroll
                for (int ni = 0; ni < 8; ni++) {
                    int nr = ni*8 + g;
                    uint32_t bf[2];
                    bf[0] = Kk[nr*16 + swz(nr, ks*2)*4 + t];
                    bf[1] = Kk[nr*16 + swz(nr, ks*2 + 1)*4 + t];
                    mma16(sacc[ni], af, bf);
                }
            }
        }

        bool diag = (kt >= 2*qt);
        #pragma unroll
        for (int ni = 0; ni < 8; ni++) {
            int col = kt*64 + ni*8 + t*2;
            float v0 = 0.12f * sacc[ni][0];
            float v1 = 0.12f * sacc[ni][1];
            float v2 = 0.12f * sacc[ni][2];
            float v3 = 0.12f * sacc[ni][3];
            if (diag) {
                if (col     > grow)     v0 = -1e30f;
                if (col + 1 > grow)     v1 = -1e30f;
                if (col     > grow + 8) v2 = -1e30f;
                if (col + 1 > grow + 8) v3 = -1e30f;
            }
            sacc[ni][0] = v0; sacc[ni][1] = v1; sacc[ni][2] = v2; sacc[ni][3] = v3;
        }

        float rm0 = -1e30f, rm1 = -1e30f;
        #pragma unroll
        for (int ni = 0; ni < 8; ni++) {
            rm0 = fmaxf(rm0, fmaxf(sacc[ni][0], sacc[ni][1]));
            rm1 = fmaxf(rm1, fmaxf(sacc[ni][2], sacc[ni][3]));
        }
        rm0 = fmaxf(rm0, __shfl_xor_sync(0xffffffff, rm0, 1));
        rm0 = fmaxf(rm0, __shfl_xor_sync(0xffffffff, rm0, 2));
        rm1 = fmaxf(rm1, __shfl_xor_sync(0xffffffff, rm1, 1));
        rm1 = fmaxf(rm1, __shfl_xor_sync(0xffffffff, rm1, 2));

        float mn0 = fmaxf(m0, rm0), mn1 = fmaxf(m1, rm1);
        float sc0 = __expf(m0 - mn0), sc1 = __expf(m1 - mn1);
        m0 = mn0; m1 = mn1;

        float ls0 = 0.f, ls1 = 0.f;
        uint32_t phg[8], phg8[8];
        #pragma unroll
        for (int ni = 0; ni < 8; ni++) {
            float p0 = __expf(sacc[ni][0] - mn0);
            float p1 = __expf(sacc[ni][1] - mn0);
            float p2 = __expf(sacc[ni][2] - mn1);
            float p3 = __expf(sacc[ni][3] - mn1);
            ls0 += p0 + p1; ls1 += p2 + p3;
            phg[ni]  = packh2(p0, p1);
            phg8[ni] = packh2(p2, p3);
        }
        ls0 += __shfl_xor_sync(0xffffffff, ls0, 1);
        ls0 += __shfl_xor_sync(0xffffffff, ls0, 2);
        ls1 += __shfl_xor_sync(0xffffffff, ls1, 1);
        ls1 += __shfl_xor_sync(0xffffffff, ls1, 2);
        l0 = l0*sc0 + ls0;
        l1 = l1*sc1 + ls1;

        #pragma unroll
        for (int ni = 0; ni < 16; ni++) {
            oacc[ni][0] *= sc0; oacc[ni][1] *= sc0;
            oacc[ni][2] *= sc1; oacc[ni][3] *= sc1;
        }

        #pragma unroll
        for (int kk = 0; kk < 4; kk++) {
            uint32_t af[4] = { phg[2*kk], phg8[2*kk], phg[2*kk+1], phg8[2*kk+1] };
            const uint32_t* Vk = Vc + (kk >> 1)*2048;
            int ks = kk & 1;
            #pragma unroll
            for (int ni = 0; ni < 16; ni++) {
                int nr = ni*8 + g;
                uint32_t bf[2];
                bf[0] = Vk[nr*16 + swz(nr, ks*2)*4 + t];
                bf[1] = Vk[nr*16 + swz(nr, ks*2 + 1)*4 + t];
                mma16(oacc[ni], af, bf);
            }
        }

        __syncthreads();
        if (kt + 2 < NT) issueKV(kt + 2);
    }

    float inv0 = 1.f / l0, inv1 = 1.f / l1;
    long base0 = ((long)b*T_ + grow) * D_ + h*HD_;
    long base1 = base0 + 8L*D_;
    #pragma unroll
    for (int ni = 0; ni < 16; ni++) {
        int col = ni*8 + t*2;
        *(uint32_t*)&att[base0 + col] = packh2(oacc[ni][0]*inv0, oacc[ni][1]*inv0);
        *(uint32_t*)&att[base1 + col] = packh2(oacc[ni][2]*inv1, oacc[ni][3]*inv1);
    }
}

// =================================================================================
// fp16 tensor-core GEMM (m16n8k16, fp32 accum), cp.async 4-stage pipeline.
// EPI: 0=store half, 1=accumulate into float C, 2=relu^2 store half,
//      5=split-K atomicAdd into float C (blockIdx.z = K-split; aZ/bZ = col offset)
// =================================================================================
template<int EPI, int MT>
__global__ void
__launch_bounds__(MT == 4 ? 512 : 256, MT == 4 ? 1 : 2)
gpt_gemm(const __half* __restrict__ A, const __half* __restrict__ Bm, void* __restrict__ Cv,
         float* __restrict__ C2,
         int K, int lda, int ldb, int ldc,
         long aZ, long bZ, int zdiv, long c1, long c2, float alpha, int ktri)
{
    constexpr int THREADS = (MT == 4) ? 512 : 256;
    constexpr int BM = MT * 64;
    constexpr int AROWS = THREADS / 4;
    constexpr int APASS = BM / AROWS;
    constexpr int BPASS = 128 / AROWS;

    const int m0 = blockIdx.y * BM, n0 = blockIdx.x * 128;

    int z = blockIdx.z;
    A  += (long)z * aZ;
    Bm += (long)z * bZ;
    long coff = (long)(z / zdiv) * c1 + (long)(z % zdiv) * c2;
    float*  Cf = (float*)Cv + coff;
    __half* Ch = (__half*)Cv + coff;

    const int tid  = threadIdx.x;
    const int lane = tid & 31, warp = tid >> 5;
    const int wm = warp >> 2, wn = warp & 3;
    const int g = lane >> 2, t = lane & 3;

    extern __shared__ uint32_t smem[];
    uint32_t* As = smem;
    uint32_t* Bs = smem + NSTAGE * BM * 16;
    uint32_t as0 = (uint32_t)__cvta_generic_to_shared(As);
    uint32_t bs0 = (uint32_t)__cvta_generic_to_shared(Bs);

    int keff = K;
    if (ktri) { int kk = m0 + BM; keff = kk < K ? kk : K; }
    const int NT = keff / BKH;

    float acc[4][4][4];
    #pragma unroll
    for (int a = 0; a < 4; a++)
        #pragma unroll
        for (int b = 0; b < 4; b++)
            #pragma unroll
            for (int c = 0; c < 4; c++) acc[a][b][c] = 0.f;

    const int ar  = tid >> 2;
    const int acg = tid & 3;
    const __half* apB = A  + (long)(m0 + ar) * lda + acg*8;
    const __half* bpB = Bm + (long)(n0 + ar) * ldb + acg*8;

    auto issue = [&](int kt) {
        int s = kt % NSTAGE;
        const __half* ap = apB + kt*BKH;
        #pragma unroll
        for (int j = 0; j < APASS; j++) {
            int r = ar + AROWS*j;
            cp16(as0 + 4u*(s*BM*16 + r*16 + swz(r, acg)*4), ap + (long)(AROWS*j) * lda);
        }
        const __half* bp = bpB + kt*BKH;
        #pragma unroll
        for (int j = 0; j < BPASS; j++) {
            int r = ar + AROWS*j;
            cp16(bs0 + 4u*(s*128*16 + r*16 + swz(r, acg)*4), bp + (long)(AROWS*j) * ldb);
        }
        asm volatile("cp.async.commit_group;" ::: "memory");
    };

    issue(0); issue(1); issue(2);

    for (int kt = 0; kt < NT; kt++) {
        if (kt + 1 >= NT)      asm volatile("cp.async.wait_group 0;" ::: "memory");
        else if (kt + 2 >= NT) asm volatile("cp.async.wait_group 1;" ::: "memory");
        else                   asm volatile("cp.async.wait_group 2;" ::: "memory");
        __syncthreads();

        const uint32_t* Ab = As + (kt % NSTAGE) * BM * 16;
        const uint32_t* Bb = Bs + (kt % NSTAGE) * 128 * 16;
        #pragma unroll
        for (int ks = 0; ks < 2; ks++) {
            uint32_t af[4][4];
            #pragma unroll
            for (int mi = 0; mi < 4; mi++) {
                int r0 = wm*64 + mi*16 + g;
                int s0 = swz(r0, ks*2)*4 + t;
                int s1 = swz(r0, ks*2 + 1)*4 + t;
                af[mi][0] = Ab[r0*16 + s0];
                af[mi][1] = Ab[(r0+8)*16 + s0];
                af[mi][2] = Ab[r0*16 + s1];
                af[mi][3] = Ab[(r0+8)*16 + s1];
            }
            uint32_t bf[4][2];
            #pragma unroll
            for (int ni = 0; ni < 4; ni++) {
                int nr = wn*32 + ni*8 + g;
                bf[ni][0] = Bb[nr*16 + swz(nr, ks*2)*4 + t];
                bf[ni][1] = Bb[nr*16 + swz(nr, ks*2 + 1)*4 + t];
            }
            #pragma unroll
            for (int mi = 0; mi < 4; mi++)
                #pragma unroll
                for (int ni = 0; ni < 4; ni++)
                    mma16(acc[mi][ni], af[mi], bf[ni]);
        }

        if (kt + NSTAGE - 1 < NT) issue(kt + NSTAGE - 1);
    }

    // ---- epilogue ----
    #pragma unroll
    for (int mi = 0; mi < 4; mi++) {
        int row = m0 + wm*64 + mi*16 + g;
        #pragma unroll
        for (int ni = 0; ni < 4; ni++) {
            int col = n0 + wn*32 + ni*8 + t*2;
            float* a4 = acc[mi][ni];
            #pragma unroll
            for (int half_ = 0; half_ < 2; half_++) {
                int r = row + half_ * 8;
                float c0 = a4[half_*2 + 0], c1 = a4[half_*2 + 1];
                if (EPI == 0) {
                    *(__half2*)&Ch[(long)r * ldc + col] = __floats2half2_rn(c0, c1);
                } else if (EPI == 2) {
                    float r0 = fmaxf(c0, 0.f), r1 = fmaxf(c1, 0.f);
                    *(__half2*)&Ch[(long)r * ldc + col] = __floats2half2_rn(r0*r0, r1*r1);
                } else if (EPI == 5) {
                    atomicAdd(&Cf[(long)r * ldc + col],     c0);
                    atomicAdd(&Cf[(long)r * ldc + col + 1], c1);
                } else {  // EPI == 1
                    float* cp = &Cf[(long)r * ldc + col];
                    float2 o = *(float2*)cp;
                    *(float2*)cp = make_float2(o.x + c0, o.y + c1);
                }
            }
        }
    }
}

// ---------------- final norm -> output ----------------
__global__ __launch_bounds__(256)
void gpt_finalnorm(const float* __restrict__ x, float* __restrict__ out)
{
    __shared__ float red[256];
    int tid = threadIdx.x;
    const float* xr = x + (long)blockIdx.x * D_;
    float a0 = xr[tid], a1 = xr[tid + 256], a2 = xr[tid + 512];
    float ss = blockReduceSum256(a0*a0 + a1*a1 + a2*a2, red);
    float r = rsqrtf(ss / (float)D_ + EPSF);
    float* yr = out + (long)blockIdx.x * D_;
    yr[tid] = a0 * r; yr[tid + 256] = a1 * r; yr[tid + 512] = a2 * r;
}

// ---------------- host orchestration ----------------
#define SMEM4 (NSTAGE * (256 + 128) * 16 * 4)   // 98304
#define SMEM2 (NSTAGE * (128 + 128) * 16 * 4)   // 65536
#define SMEMF ((8192 + 2*8192) * 4)             // 98304 (flash)

extern "C" void kernel_launch(void* const* d_in, const int* in_sizes, int n_in,
                              void* d_out, int out_size)
{
    const int*   seq         = (const int*)  d_in[0];
    const float* embed_w     = (const float*)d_in[1];
    const float* ve_w        = (const float*)d_in[2];
    const float* qkv_w       = (const float*)d_in[3];
    const float* attn_proj_w = (const float*)d_in[4];
    const float* mlp_fc_w    = (const float*)d_in[5];
    const float* mlp_proj_w  = (const float*)d_in[6];
    const float* scalars     = (const float*)d_in[7];

    cudaFuncSetAttribute(gpt_gemm<0,4>, cudaFuncAttributeMaxDynamicSharedMemorySize, SMEM4);
    cudaFuncSetAttribute(gpt_gemm<2,4>, cudaFuncAttributeMaxDynamicSharedMemorySize, SMEM4);
    cudaFuncSetAttribute(gpt_gemm<5,2>, cudaFuncAttributeMaxDynamicSharedMemorySize, SMEM2);
    cudaFuncSetAttribute(gpt_flash,     cudaFuncAttributeMaxDynamicSharedMemorySize, SMEMF);

    float *x, *x0, *skips, *ve;
    float2 *rtab;
    __half *xn, *qkv, *q, *k, *vt, *att, *hbuf;
    __half *qkvw, *aprojw, *fcw, *mprojw;
    cudaGetSymbolAddress((void**)&x,      g_x);
    cudaGetSymbolAddress((void**)&x0,     g_x0);
    cudaGetSymbolAddress((void**)&xn,     g_xn);
    cudaGetSymbolAddress((void**)&skips,  g_skips);
    cudaGetSymbolAddress((void**)&ve,     g_ve);
    cudaGetSymbolAddress((void**)&qkv,    g_qkv);
    cudaGetSymbolAddress((void**)&q,      g_q);
    cudaGetSymbolAddress((void**)&k,      g_k);
    cudaGetSymbolAddress((void**)&vt,     g_vt);
    cudaGetSymbolAddress((void**)&att,    g_att);
    cudaGetSymbolAddress((void**)&hbuf,   g_hbuf);
    cudaGetSymbolAddress((void**)&rtab,   g_rtab);
    cudaGetSymbolAddress((void**)&qkvw,   g_qkvw);
    cudaGetSymbolAddress((void**)&aprojw, g_aprojw);
    cudaGetSymbolAddress((void**)&fcw,    g_fcw);
    cudaGetSymbolAddress((void**)&mprojw, g_mprojw);

    const int NTOK = B_ * T_;   // 4096

    gpt_cvtw<<<2048, 256>>>(qkv_w,       qkvw,   (long)L_*3*H_*HD_*D_);
    gpt_cvtw<<<2048, 256>>>(attn_proj_w, aprojw, (long)L_*D_*H_*HD_);
    gpt_cvtw<<<2048, 256>>>(mlp_fc_w,    fcw,    (long)L_*4*D_*D_);
    gpt_cvtw<<<2048, 256>>>(mlp_proj_w,  mprojw, (long)L_*D_*4*D_);
    gpt_ropetab<<<128, 256>>>(rtab);

    gpt_embed<<<NTOK, 256>>>(seq, embed_w, ve_w, x, x0, ve);

    for (int i = 0; i < L_; i++) {
        const float* skip = (i >= 6) ? (skips + (long)(11 - i) * BTD) : nullptr;
        gpt_resnorm<<<NTOK, 256>>>(x, x0, skip, scalars, i, xn);

        if (i != 7) {
            // qkv = xn @ W_qkv^T : [4096,768] x [2304,768]^T  -> half
            gpt_gemm<0,4><<<dim3(18, 16, 1), 512, SMEM4>>>(
                xn, qkvw + (long)i * 3 * H_ * HD_ * D_, qkv, nullptr,
                D_, D_, D_, 3*H_*HD_, 0, 0, 1, 0, 0, 1.f, 0);

            const float* vep = nullptr;
            if (i < 3)       vep = ve + (long)i * BTD;
            else if (i >= 9) vep = ve + (long)(i - 9) * BTD;
            gpt_rope<<<B_*T_*H_/8, 256>>>(qkv, vep, scalars, i, q, k, vt, rtab);

            // fused flash attention -> att (half)
            gpt_flash<<<dim3(8, B_*H_), 256, SMEMF>>>(q, k, vt, att);

            // x += att @ W_proj^T  (split-K=2, atomicAdd)
            gpt_gemm<5,2><<<dim3(6, 32, 2), 256, SMEM2>>>(
                att, aprojw + (long)i * D_ * H_ * HD_, x, nullptr,
                (H_*HD_)/2, H_*HD_, H_*HD_, D_,
                (H_*HD_)/2, (H_*HD_)/2, 1, 0, 0, 1.f, 0);

            gpt_rmsnorm<<<NTOK, 256>>>(x, xn);
        }

        // h = relu(xn @ W_fc^T)^2 : [4096,768] x [3072,768]^T -> half
        gpt_gemm<2,4><<<dim3(24, 16, 1), 512, SMEM4>>>(
            xn, fcw + (long)i * 4 * D_ * D_, hbuf, nullptr,
            D_, D_, D_, 4*D_, 0, 0, 1, 0, 0, 1.f, 0);

        // x += h @ W_proj^T  (split-K=2, atomicAdd)
        gpt_gemm<5,2><<<dim3(6, 32, 2), 256, SMEM2>>>(
            hbuf, mprojw + (long)i * D_ * 4 * D_, x, nullptr,
            (4*D_)/2, 4*D_, 4*D_, D_,
            (4*D_)/2, (4*D_)/2, 1, 0, 0, 1.f, 0);

        if (i < 6) gpt_copy<<<BTD/1024, 256>>>(skips + (long)i * BTD, x);
    }

    gpt_finalnorm<<<NTOK, 256>>>(x, (float*)d_out);
}

// round 17
// speedup vs baseline: 1.0361x; 1.0333x over previous
#include <cuda_runtime.h>
#include <cuda_fp16.h>
#include <math.h>
#include <stdint.h>

#define B_  4
#define T_  1024
#define D_  768
#define H_  6
#define HD_ 128
#define L_  12
#define BTD (B_*T_*D_)          // 3145728
#define EPSF 1.1920929e-07f
#define BKH 32                  // k-halfs per tile (16 uint32 words)
#define NSTAGE 4

// ---------------- scratch (device globals; no allocation allowed) ----------------
__device__ float  g_x   [BTD];
__device__ float  g_x0  [BTD];
__device__ __half g_xn  [BTD];
__device__ float  g_skips[6*BTD];
__device__ float  g_ve  [3*BTD];
__device__ __half g_qkv [B_*T_*3*H_*HD_];      // [bt][which*768 + h*128 + hd]
__device__ __half g_q   [B_*H_*T_*HD_];        // [b][h][t][hd]
__device__ __half g_k   [B_*H_*T_*HD_];
__device__ __half g_vt  [B_*H_*HD_*T_];        // [b][h][hd][t]  (transposed V)
__device__ __half g_att [BTD];                 // [b][t][h*128+hd]
__device__ __half g_hbuf[B_*T_*4*D_];          // [bt][3072]
__device__ float2 g_rtab[T_*32];               // rope cos/sin table
// fp16 weight mirrors
__device__ __half g_qkvw [L_*3*H_*HD_*D_];
__device__ __half g_aprojw[L_*D_*H_*HD_];
__device__ __half g_fcw  [L_*4*D_*D_];
__device__ __half g_mprojw[L_*D_*4*D_];

// ---------------- helpers ----------------
__device__ __forceinline__ float blockReduceSum256(float v, float* red) {
    int tid = threadIdx.x;
    red[tid] = v; __syncthreads();
    for (int s = 128; s > 0; s >>= 1) {
        if (tid < s) red[tid] += red[tid + s];
        __syncthreads();
    }
    float r = red[0]; __syncthreads();
    return r;
}

__device__ __forceinline__ void mma16(float* c, const uint32_t* a, const uint32_t* b) {
    asm volatile(
        "mma.sync.aligned.m16n8k16.row.col.f32.f16.f16.f32 "
        "{%0,%1,%2,%3}, {%4,%5,%6,%7}, {%8,%9}, {%0,%1,%2,%3};"
        : "+f"(c[0]), "+f"(c[1]), "+f"(c[2]), "+f"(c[3])
        : "r"(a[0]), "r"(a[1]), "r"(a[2]), "r"(a[3]), "r"(b[0]), "r"(b[1]));
}

__device__ __forceinline__ void cp16(uint32_t saddr, const void* gptr) {
    asm volatile("cp.async.cg.shared.global [%0], [%1], 16;" :: "r"(saddr), "l"(gptr));
}

// swizzle: column-group permutation within a 16-word row
__device__ __forceinline__ int swz(int r, int cg) { return cg ^ ((r >> 1) & 3); }

__device__ __forceinline__ uint32_t packh2(float a, float b) {
    __half2 h = __floats2half2_rn(a, b);
    return *(uint32_t*)&h;
}

// ---------------- weight conversion fp32 -> fp16 (rne) ----------------
__global__ __launch_bounds__(256)
void gpt_cvtw(const float* __restrict__ src, __half* __restrict__ dst, long n)
{
    long i = ((long)blockIdx.x * 256 + threadIdx.x) * 4;
    long stride = (long)gridDim.x * 1024;
    for (; i < n; i += stride) {
        float4 v = *(const float4*)&src[i];
        __half2* d = (__half2*)&dst[i];
        d[0] = __floats2half2_rn(v.x, v.y);
        d[1] = __floats2half2_rn(v.z, v.w);
    }
}

// ---------------- rope table: cos/sin(t * freq_j), layer-invariant ----------------
__global__ __launch_bounds__(256)
void gpt_ropetab(float2* __restrict__ rtab)
{
    int i = blockIdx.x * 256 + threadIdx.x;   // t*32 + j, 32768 entries
    int t = i >> 5, j = i & 31;
    float freq = exp2f(-10.0f * (float)j / 31.0f);
    float sn, cs;
    sincosf((float)t * freq, &sn, &cs);
    rtab[i] = make_float2(cs, sn);
}

// ---------------- embedding + norm + ve gather ----------------
__global__ __launch_bounds__(256)
void gpt_embed(const int* __restrict__ seq, const float* __restrict__ ew,
               const float* __restrict__ vew,
               float* __restrict__ x, float* __restrict__ x0, float* __restrict__ ve)
{
    __shared__ float red[256];
    int bt = blockIdx.x;
    int tid = threadIdx.x;
    int idx = seq[bt];
    const float* er = ew + (long)idx * D_;
    float a0 = er[tid], a1 = er[tid + 256], a2 = er[tid + 512];
    float ss = blockReduceSum256(a0*a0 + a1*a1 + a2*a2, red);
    float r = rsqrtf(ss / (float)D_ + EPSF);
    long o = (long)bt * D_;
    x0[o + tid]       = a0 * r;  x[o + tid]       = a0 * r;
    x0[o + tid + 256] = a1 * r;  x[o + tid + 256] = a1 * r;
    x0[o + tid + 512] = a2 * r;  x[o + tid + 512] = a2 * r;
    #pragma unroll
    for (int j = 0; j < 3; j++) {
        const float* vr = vew + ((long)j * 50257 + idx) * D_;
        float* vo = ve + ((long)j * (B_*T_) + bt) * D_;
        for (int d = tid; d < D_; d += 256) vo[d] = vr[d];
    }
}

// ------- fused residual + rms norm: x = l0*(x + sw*skip) + l1*x0 ; xn = h(norm(x))
__global__ __launch_bounds__(256)
void gpt_resnorm(float* __restrict__ x, const float* __restrict__ x0,
                 const float* __restrict__ skip, const float* __restrict__ scalars,
                 int layer, __half* __restrict__ xn)
{
    __shared__ float red[256];
    float l0 = scalars[L_ + 2*layer];
    float l1 = scalars[L_ + 2*layer + 1];
    float sw = skip ? scalars[layer - 6] : 0.f;
    int tid = threadIdx.x;
    long o = (long)blockIdx.x * D_;
    float a[3];
    #pragma unroll
    for (int j = 0; j < 3; j++) {
        long i = o + tid + j*256;
        float v = x[i];
        if (skip) v += sw * skip[i];
        v = l0 * v + l1 * x0[i];
        x[i] = v;
        a[j] = v;
    }
    float ss = blockReduceSum256(a[0]*a[0] + a[1]*a[1] + a[2]*a[2], red);
    float r = rsqrtf(ss / (float)D_ + EPSF);
    #pragma unroll
    for (int j = 0; j < 3; j++)
        xn[o + tid + j*256] = __float2half_rn(a[j] * r);
}

// ---------------- rms norm (row = 768), output fp16 ----------------
__global__ __launch_bounds__(256)
void gpt_rmsnorm(const float* __restrict__ x, __half* __restrict__ y)
{
    __shared__ float red[256];
    int tid = threadIdx.x;
    const float* xr = x + (long)blockIdx.x * D_;
    float a0 = xr[tid], a1 = xr[tid + 256], a2 = xr[tid + 512];
    float ss = blockReduceSum256(a0*a0 + a1*a1 + a2*a2, red);
    float r = rsqrtf(ss / (float)D_ + EPSF);
    __half* yr = y + (long)blockIdx.x * D_;
    yr[tid]       = __float2half_rn(a0 * r);
    yr[tid + 256] = __float2half_rn(a1 * r);
    yr[tid + 512] = __float2half_rn(a2 * r);
}

// ---------------- copy (for skip buffers) ----------------
__global__ __launch_bounds__(256)
void gpt_copy(float* __restrict__ dst, const float* __restrict__ src)
{
    long i = ((long)blockIdx.x * 256 + threadIdx.x) * 4;
    float4 v = *(const float4*)&src[i];
    *(float4*)&dst[i] = v;
}

// ------- warp-level rope: one warp per (b,t,h); lane owns hd = lane + 32*j -------
__global__ __launch_bounds__(256)
void gpt_rope(const __half* __restrict__ qkv, const float* __restrict__ ve,
              const float* __restrict__ scalars, int layer,
              __half* __restrict__ q, __half* __restrict__ k, __half* __restrict__ vt,
              const float2* __restrict__ rtab)
{
    int z = blockIdx.x * 8 + (threadIdx.x >> 5);
    int lane = threadIdx.x & 31;
    int h = z % H_;
    int t = (z / H_) % T_;
    int b = z / (H_ * T_);
    long bt = (long)b * T_ + t;
    const __half* base = qkv + bt * (3*H_*HD_) + h * HD_;

    float qv[4], kv[4], vv[4];
    #pragma unroll
    for (int j = 0; j < 4; j++) {
        qv[j] = __half2float(base[lane + 32*j]);
        kv[j] = __half2float(base[H_*HD_ + lane + 32*j]);
        vv[j] = __half2float(base[2*H_*HD_ + lane + 32*j]);
    }
    float sq = qv[0]*qv[0] + qv[1]*qv[1] + qv[2]*qv[2] + qv[3]*qv[3];
    float sk = kv[0]*kv[0] + kv[1]*kv[1] + kv[2]*kv[2] + kv[3]*kv[3];
    #pragma unroll
    for (int s = 16; s > 0; s >>= 1) {
        sq += __shfl_xor_sync(0xffffffff, sq, s);
        sk += __shfl_xor_sync(0xffffffff, sk, s);
    }
    float rnq = rsqrtf(sq / (float)HD_ + EPSF);
    float rnk = rsqrtf(sk / (float)HD_ + EPSF);
    #pragma unroll
    for (int j = 0; j < 4; j++) { qv[j] *= rnq; kv[j] *= rnk; }

    float2 cs = rtab[t*32 + lane];
    float oq0 =  qv[0]*cs.x + qv[2]*cs.y;
    float oq2 = -qv[0]*cs.y + qv[2]*cs.x;
    float ok0 =  kv[0]*cs.x + kv[2]*cs.y;
    float ok2 = -kv[0]*cs.y + kv[2]*cs.x;

    long o = (((long)b * H_ + h) * T_ + t) * HD_;
    q[o + lane]      = __float2half_rn(oq0);
    q[o + lane + 32] = __float2half_rn(qv[1]);
    q[o + lane + 64] = __float2half_rn(oq2);
    q[o + lane + 96] = __float2half_rn(qv[3]);
    k[o + lane]      = __float2half_rn(ok0);
    k[o + lane + 32] = __float2half_rn(kv[1]);
    k[o + lane + 64] = __float2half_rn(ok2);
    k[o + lane + 96] = __float2half_rn(kv[3]);

    float sa0 = scalars[3*L_ + 2*layer];
    float sa1 = scalars[3*L_ + 2*layer + 1];
    long vbase = ((long)b * H_ + h) * HD_;
    #pragma unroll
    for (int j = 0; j < 4; j++) {
        float vo = sa0 * vv[j];
        if (ve) vo += sa1 * ve[bt * D_ + h * HD_ + lane + 32*j];
        vt[(vbase + lane + 32*j) * T_ + t] = __float2half_rn(vo);
    }
}

// =================================================================================
// Fused flash attention: 128 q-rows per CTA (8 warps), K/V tiles of 64, online
// softmax, double-buffered cp.async K/V. Q/K: [b][h][t][hd]; V: [b][h][hd][t].
// =================================================================================
__global__ void __launch_bounds__(256, 1)
gpt_flash(const __half* __restrict__ Q, const __half* __restrict__ K,
          const __half* __restrict__ Vt, __half* __restrict__ att)
{
    const int qt = 7 - blockIdx.x;            // heavy tiles first
    const int bh = blockIdx.y;
    const int b = bh / H_, h = bh % H_;
    const int tid = threadIdx.x;
    const int w = tid >> 5, lane = tid & 31;
    const int g = lane >> 2, t = lane & 3;

    const __half* Qb = Q  + (((long)bh * T_) + qt*128) * HD_;
    const __half* Kb = K  + (long)bh * T_ * HD_;
    const __half* Vb = Vt + (long)bh * HD_ * T_;

    extern __shared__ uint32_t sm[];
    uint32_t sbase = (uint32_t)__cvta_generic_to_shared(sm);

    #pragma unroll
    for (int j = 0; j < 8; j++) {
        int i = tid + j*256;
        int row = i >> 4, c16 = i & 15;
        int kc = c16 >> 2, wg = c16 & 3;
        uint32_t word = (kc*128 + row)*16 + swz(row, wg)*4;
        cp16(sbase + 4u*word, Qb + row*HD_ + c16*8);
    }
    asm volatile("cp.async.commit_group;" ::: "memory");

    const int NT = 2*qt + 2;

    auto issueKV = [&](int kt) {
        int s = kt & 1;
        uint32_t kw0 = 8192 + s*8192;
        #pragma unroll
        for (int j = 0; j < 4; j++) {
            int i = tid + j*256;
            int row = i >> 4, c16 = i & 15;
            int kc = c16 >> 2, wg = c16 & 3;
            uint32_t word = kw0 + (kc*64 + row)*16 + swz(row, wg)*4;
            cp16(sbase + 4u*word, Kb + (long)(kt*64 + row)*HD_ + c16*8);
        }
        uint32_t vw0 = 12288 + s*8192;
        #pragma unroll
        for (int j = 0; j < 4; j++) {
            int i = tid + j*256;
            int row = i >> 3, c16 = i & 7;
            int kc = c16 >> 2, wg = c16 & 3;
            uint32_t word = vw0 + (kc*128 + row)*16 + swz(row, wg)*4;
            cp16(sbase + 4u*word, Vb + (long)row*T_ + kt*64 + c16*8);
        }
        asm volatile("cp.async.commit_group;" ::: "memory");
    };

    issueKV(0); issueKV(1);

    float m0 = -1e30f, m1 = -1e30f, l0 = 0.f, l1 = 0.f;
    float oacc[16][4];
    #pragma unroll
    for (int a = 0; a < 16; a++)
        #pragma unroll
        for (int c = 0; c < 4; c++) oacc[a][c] = 0.f;

    const int r0 = w*16 + g;
    const int grow = qt*128 + r0;

    for (int kt = 0; kt < NT; kt++) {
        if (kt + 1 < NT) asm volatile("cp.async.wait_group 1;" ::: "memory");
        else             asm volatile("cp.async.wait_group 0;" ::: "memory");
        __syncthreads();

        const uint32_t* Kc = sm + 8192 + (kt & 1)*8192;
        const uint32_t* Vc = sm + 12288 + (kt & 1)*8192;

        float sacc[8][4];
        #pragma unroll
        for (int a = 0; a < 8; a++)
            #pragma unroll
            for (int c = 0; c < 4; c++) sacc[a][c] = 0.f;

        #pragma unroll
        for (int kc = 0; kc < 4; kc++) {
            const uint32_t* Qc = sm + kc*2048;
            const uint32_t* Kk = Kc + kc*1024;
            #pragma unroll
            for (int ks = 0; ks < 2; ks++) {
                int s0 = swz(r0, ks*2)*4 + t;
                int s1 = swz(r0, ks*2 + 1)*4 + t;
                uint32_t af[4];
                af[0] = Qc[r0*16 + s0];
                af[1] = Qc[(r0+8)*16 + s0];
                af[2] = Qc[r0*16 + s1];
                af[3] = Qc[(r0+8)*16 + s1];
                #pragma unroll
                for (int ni = 0; ni < 8; ni++) {
                    int nr = ni*8 + g;
                    uint32_t bf[2];
                    bf[0] = Kk[nr*16 + swz(nr, ks*2)*4 + t];
                    bf[1] = Kk[nr*16 + swz(nr, ks*2 + 1)*4 + t];
                    mma16(sacc[ni], af, bf);
                }
            }
        }

        bool diag = (kt >= 2*qt);
        #pragma unroll
        for (int ni = 0; ni < 8; ni++) {
            int col = kt*64 + ni*8 + t*2;
            float v0 = 0.12f * sacc[ni][0];
            float v1 = 0.12f * sacc[ni][1];
            float v2 = 0.12f * sacc[ni][2];
            float v3 = 0.12f * sacc[ni][3];
            if (diag) {
                if (col     > grow)     v0 = -1e30f;
                if (col + 1 > grow)     v1 = -1e30f;
                if (col     > grow + 8) v2 = -1e30f;
                if (col + 1 > grow + 8) v3 = -1e30f;
            }
            sacc[ni][0] = v0; sacc[ni][1] = v1; sacc[ni][2] = v2; sacc[ni][3] = v3;
        }

        float rm0 = -1e30f, rm1 = -1e30f;
        #pragma unroll
        for (int ni = 0; ni < 8; ni++) {
            rm0 = fmaxf(rm0, fmaxf(sacc[ni][0], sacc[ni][1]));
            rm1 = fmaxf(rm1, fmaxf(sacc[ni][2], sacc[ni][3]));
        }
        rm0 = fmaxf(rm0, __shfl_xor_sync(0xffffffff, rm0, 1));
        rm0 = fmaxf(rm0, __shfl_xor_sync(0xffffffff, rm0, 2));
        rm1 = fmaxf(rm1, __shfl_xor_sync(0xffffffff, rm1, 1));
        rm1 = fmaxf(rm1, __shfl_xor_sync(0xffffffff, rm1, 2));

        float mn0 = fmaxf(m0, rm0), mn1 = fmaxf(m1, rm1);
        float sc0 = __expf(m0 - mn0), sc1 = __expf(m1 - mn1);
        m0 = mn0; m1 = mn1;

        float ls0 = 0.f, ls1 = 0.f;
        uint32_t phg[8], phg8[8];
        #pragma unroll
        for (int ni = 0; ni < 8; ni++) {
            float p0 = __expf(sacc[ni][0] - mn0);
            float p1 = __expf(sacc[ni][1] - mn0);
            float p2 = __expf(sacc[ni][2] - mn1);
            float p3 = __expf(sacc[ni][3] - mn1);
            ls0 += p0 + p1; ls1 += p2 + p3;
            phg[ni]  = packh2(p0, p1);
            phg8[ni] = packh2(p2, p3);
        }
        ls0 += __shfl_xor_sync(0xffffffff, ls0, 1);
        ls0 += __shfl_xor_sync(0xffffffff, ls0, 2);
        ls1 += __shfl_xor_sync(0xffffffff, ls1, 1);
        ls1 += __shfl_xor_sync(0xffffffff, ls1, 2);
        l0 = l0*sc0 + ls0;
        l1 = l1*sc1 + ls1;

        #pragma unroll
        for (int ni = 0; ni < 16; ni++) {
            oacc[ni][0] *= sc0; oacc[ni][1] *= sc0;
            oacc[ni][2] *= sc1; oacc[ni][3] *= sc1;
        }

        #pragma unroll
        for (int kk = 0; kk < 4; kk++) {
            uint32_t af[4] = { phg[2*kk], phg8[2*kk], phg[2*kk+1], phg8[2*kk+1] };
            const uint32_t* Vk = Vc + (kk >> 1)*2048;
            int ks = kk & 1;
            #pragma unroll
            for (int ni = 0; ni < 16; ni++) {
                int nr = ni*8 + g;
                uint32_t bf[2];
                bf[0] = Vk[nr*16 + swz(nr, ks*2)*4 + t];
                bf[1] = Vk[nr*16 + swz(nr, ks*2 + 1)*4 + t];
                mma16(oacc[ni], af, bf);
            }
        }

        __syncthreads();
        if (kt + 2 < NT) issueKV(kt + 2);
    }

    float inv0 = 1.f / l0, inv1 = 1.f / l1;
    long base0 = ((long)b*T_ + grow) * D_ + h*HD_;
    long base1 = base0 + 8L*D_;
    #pragma unroll
    for (int ni = 0; ni < 16; ni++) {
        int col = ni*8 + t*2;
        *(uint32_t*)&att[base0 + col] = packh2(oacc[ni][0]*inv0, oacc[ni][1]*inv0);
        *(uint32_t*)&att[base1 + col] = packh2(oacc[ni][2]*inv1, oacc[ni][3]*inv1);
    }
}

// =================================================================================
// fp16 tensor-core GEMM (m16n8k16, fp32 accum), cp.async 4-stage pipeline.
// 64x64 warp tiles for crossbar efficiency (0.0625 B/MAC).
// MT=4: 256x128 block tile, 8 warps (256 thr, grid 4x2), 1 CTA/SM
// MT=2: 128x128 block tile, 4 warps (128 thr, grid 2x2), 2 CTA/SM
// C[m][n] = sum_k A[m][k] * B[n][k]
// EPI: 0=store half, 1=accumulate into float C, 2=relu^2 store half,
//      5=split-K atomicAdd into float C (blockIdx.z = K-split; aZ/bZ = col offset)
// =================================================================================
template<int EPI, int MT>
__global__ void
__launch_bounds__(MT == 4 ? 256 : 128, MT == 4 ? 1 : 2)
gpt_gemm(const __half* __restrict__ A, const __half* __restrict__ Bm, void* __restrict__ Cv,
         float* __restrict__ C2,
         int K, int lda, int ldb, int ldc,
         long aZ, long bZ, int zdiv, long c1, long c2, float alpha, int ktri)
{
    constexpr int THREADS = (MT == 4) ? 256 : 128;
    constexpr int BM = MT * 64;
    constexpr int AROWS = THREADS / 4;     // 64 or 32
    constexpr int APASS = BM / AROWS;      // 4
    constexpr int BPASS = 128 / AROWS;     // 2 or 4

    const int m0 = blockIdx.y * BM, n0 = blockIdx.x * 128;

    int z = blockIdx.z;
    A  += (long)z * aZ;
    Bm += (long)z * bZ;
    long coff = (long)(z / zdiv) * c1 + (long)(z % zdiv) * c2;
    float*  Cf = (float*)Cv + coff;
    __half* Ch = (__half*)Cv + coff;

    const int tid  = threadIdx.x;
    const int lane = tid & 31, warp = tid >> 5;
    const int wm = warp >> 1, wn = warp & 1;      // 4x2 (MT4) or 2x2 (MT2)
    const int g = lane >> 2, t = lane & 3;

    extern __shared__ uint32_t smem[];
    uint32_t* As = smem;
    uint32_t* Bs = smem + NSTAGE * BM * 16;
    uint32_t as0 = (uint32_t)__cvta_generic_to_shared(As);
    uint32_t bs0 = (uint32_t)__cvta_generic_to_shared(Bs);

    int keff = K;
    if (ktri) { int kk = m0 + BM; keff = kk < K ? kk : K; }
    const int NT = keff / BKH;

    float acc[4][8][4];
    #pragma unroll
    for (int a = 0; a < 4; a++)
        #pragma unroll
        for (int b = 0; b < 8; b++)
            #pragma unroll
            for (int c = 0; c < 4; c++) acc[a][b][c] = 0.f;

    const int ar  = tid >> 2;
    const int acg = tid & 3;
    const __half* apB = A  + (long)(m0 + ar) * lda + acg*8;
    const __half* bpB = Bm + (long)(n0 + ar) * ldb + acg*8;

    auto issue = [&](int kt) {
        int s = kt % NSTAGE;
        const __half* ap = apB + kt*BKH;
        #pragma unroll
        for (int j = 0; j < APASS; j++) {
            int r = ar + AROWS*j;
            cp16(as0 + 4u*(s*BM*16 + r*16 + swz(r, acg)*4), ap + (long)(AROWS*j) * lda);
        }
        const __half* bp = bpB + kt*BKH;
        #pragma unroll
        for (int j = 0; j < BPASS; j++) {
            int r = ar + AROWS*j;
            cp16(bs0 + 4u*(s*128*16 + r*16 + swz(r, acg)*4), bp + (long)(AROWS*j) * ldb);
        }
        asm volatile("cp.async.commit_group;" ::: "memory");
    };

    issue(0); issue(1); issue(2);

    for (int kt = 0; kt < NT; kt++) {
        if (kt + 1 >= NT)      asm volatile("cp.async.wait_group 0;" ::: "memory");
        else if (kt + 2 >= NT) asm volatile("cp.async.wait_group 1;" ::: "memory");
        else                   asm volatile("cp.async.wait_group 2;" ::: "memory");
        __syncthreads();

        const uint32_t* Ab = As + (kt % NSTAGE) * BM * 16;
        const uint32_t* Bb = Bs + (kt % NSTAGE) * 128 * 16;
        #pragma unroll
        for (int ks = 0; ks < 2; ks++) {
            uint32_t af[4][4];
            #pragma unroll
            for (int mi = 0; mi < 4; mi++) {
                int r0 = wm*64 + mi*16 + g;
                int s0 = swz(r0, ks*2)*4 + t;
                int s1 = swz(r0, ks*2 + 1)*4 + t;
                af[mi][0] = Ab[r0*16 + s0];
                af[mi][1] = Ab[(r0+8)*16 + s0];
                af[mi][2] = Ab[r0*16 + s1];
                af[mi][3] = Ab[(r0+8)*16 + s1];
            }
            uint32_t bf[8][2];
            #pragma unroll
            for (int ni = 0; ni < 8; ni++) {
                int nr = wn*64 + ni*8 + g;
                bf[ni][0] = Bb[nr*16 + swz(nr, ks*2)*4 + t];
                bf[ni][1] = Bb[nr*16 + swz(nr, ks*2 + 1)*4 + t];
            }
            #pragma unroll
            for (int mi = 0; mi < 4; mi++)
                #pragma unroll
                for (int ni = 0; ni < 8; ni++)
                    mma16(acc[mi][ni], af[mi], bf[ni]);
        }

        if (kt + NSTAGE - 1 < NT) issue(kt + NSTAGE - 1);
    }

    // ---- epilogue ----
    #pragma unroll
    for (int mi = 0; mi < 4; mi++) {
        int row = m0 + wm*64 + mi*16 + g;
        #pragma unroll
        for (int ni = 0; ni < 8; ni++) {
            int col = n0 + wn*64 + ni*8 + t*2;
            float* a4 = acc[mi][ni];
            #pragma unroll
            for (int half_ = 0; half_ < 2; half_++) {
                int r = row + half_ * 8;
                float c0 = a4[half_*2 + 0], c1 = a4[half_*2 + 1];
                if (EPI == 0) {
                    *(__half2*)&Ch[(long)r * ldc + col] = __floats2half2_rn(c0, c1);
                } else if (EPI == 2) {
                    float r0 = fmaxf(c0, 0.f), r1 = fmaxf(c1, 0.f);
                    *(__half2*)&Ch[(long)r * ldc + col] = __floats2half2_rn(r0*r0, r1*r1);
                } else if (EPI == 5) {
                    atomicAdd(&Cf[(long)r * ldc + col],     c0);
                    atomicAdd(&Cf[(long)r * ldc + col + 1], c1);
                } else {  // EPI == 1
                    float* cp = &Cf[(long)r * ldc + col];
                    float2 o = *(float2*)cp;
                    *(float2*)cp = make_float2(o.x + c0, o.y + c1);
                }
            }
        }
    }
}

// ---------------- final norm -> output ----------------
__global__ __launch_bounds__(256)
void gpt_finalnorm(const float* __restrict__ x, float* __restrict__ out)
{
    __shared__ float red[256];
    int tid = threadIdx.x;
    const float* xr = x + (long)blockIdx.x * D_;
    float a0 = xr[tid], a1 = xr[tid + 256], a2 = xr[tid + 512];
    float ss = blockReduceSum256(a0*a0 + a1*a1 + a2*a2, red);
    float r = rsqrtf(ss / (float)D_ + EPSF);
    float* yr = out + (long)blockIdx.x * D_;
    yr[tid] = a0 * r; yr[tid + 256] = a1 * r; yr[tid + 512] = a2 * r;
}

// ---------------- host orchestration ----------------
#define SMEM4 (NSTAGE * (256 + 128) * 16 * 4)   // 98304
#define SMEM2 (NSTAGE * (128 + 128) * 16 * 4)   // 65536
#define SMEMF ((8192 + 2*8192) * 4)             // 98304 (flash)

extern "C" void kernel_launch(void* const* d_in, const int* in_sizes, int n_in,
                              void* d_out, int out_size)
{
    const int*   seq         = (const int*)  d_in[0];
    const float* embed_w     = (const float*)d_in[1];
    const float* ve_w        = (const float*)d_in[2];
    const float* qkv_w       = (const float*)d_in[3];
    const float* attn_proj_w = (const float*)d_in[4];
    const float* mlp_fc_w    = (const float*)d_in[5];
    const float* mlp_proj_w  = (const float*)d_in[6];
    const float* scalars     = (const float*)d_in[7];

    cudaFuncSetAttribute(gpt_gemm<0,4>, cudaFuncAttributeMaxDynamicSharedMemorySize, SMEM4);
    cudaFuncSetAttribute(gpt_gemm<2,4>, cudaFuncAttributeMaxDynamicSharedMemorySize, SMEM4);
    cudaFuncSetAttribute(gpt_gemm<5,2>, cudaFuncAttributeMaxDynamicSharedMemorySize, SMEM2);
    cudaFuncSetAttribute(gpt_flash,     cudaFuncAttributeMaxDynamicSharedMemorySize, SMEMF);

    float *x, *x0, *skips, *ve;
    float2 *rtab;
    __half *xn, *qkv, *q, *k, *vt, *att, *hbuf;
    __half *qkvw, *aprojw, *fcw, *mprojw;
    cudaGetSymbolAddress((void**)&x,      g_x);
    cudaGetSymbolAddress((void**)&x0,     g_x0);
    cudaGetSymbolAddress((void**)&xn,     g_xn);
    cudaGetSymbolAddress((void**)&skips,  g_skips);
    cudaGetSymbolAddress((void**)&ve,     g_ve);
    cudaGetSymbolAddress((void**)&qkv,    g_qkv);
    cudaGetSymbolAddress((void**)&q,      g_q);
    cudaGetSymbolAddress((void**)&k,      g_k);
    cudaGetSymbolAddress((void**)&vt,     g_vt);
    cudaGetSymbolAddress((void**)&att,    g_att);
    cudaGetSymbolAddress((void**)&hbuf,   g_hbuf);
    cudaGetSymbolAddress((void**)&rtab,   g_rtab);
    cudaGetSymbolAddress((void**)&qkvw,   g_qkvw);
    cudaGetSymbolAddress((void**)&aprojw, g_aprojw);
    cudaGetSymbolAddress((void**)&fcw,    g_fcw);
    cudaGetSymbolAddress((void**)&mprojw, g_mprojw);

    const int NTOK = B_ * T_;   // 4096

    gpt_cvtw<<<2048, 256>>>(qkv_w,       qkvw,   (long)L_*3*H_*HD_*D_);
    gpt_cvtw<<<2048, 256>>>(attn_proj_w, aprojw, (long)L_*D_*H_*HD_);
    gpt_cvtw<<<2048, 256>>>(mlp_fc_w,    fcw,    (long)L_*4*D_*D_);
    gpt_cvtw<<<2048, 256>>>(mlp_proj_w,  mprojw, (long)L_*D_*4*D_);
    gpt_ropetab<<<128, 256>>>(rtab);

    gpt_embed<<<NTOK, 256>>>(seq, embed_w, ve_w, x, x0, ve);

    for (int i = 0; i < L_; i++) {
        const float* skip = (i >= 6) ? (skips + (long)(11 - i) * BTD) : nullptr;
        gpt_resnorm<<<NTOK, 256>>>(x, x0, skip, scalars, i, xn);

        if (i != 7) {
            // qkv = xn @ W_qkv^T : [4096,768] x [2304,768]^T  -> half
            gpt_gemm<0,4><<<dim3(18, 16, 1), 256, SMEM4>>>(
                xn, qkvw + (long)i * 3 * H_ * HD_ * D_, qkv, nullptr,
                D_, D_, D_, 3*H_*HD_, 0, 0, 1, 0, 0, 1.f, 0);

            const float* vep = nullptr;
            if (i < 3)       vep = ve + (long)i * BTD;
            else if (i >= 9) vep = ve + (long)(i - 9) * BTD;
            gpt_rope<<<B_*T_*H_/8, 256>>>(qkv, vep, scalars, i, q, k, vt, rtab);

            // fused flash attention -> att (half)
            gpt_flash<<<dim3(8, B_*H_), 256, SMEMF>>>(q, k, vt, att);

            // x += att @ W_proj^T  (split-K=2, atomicAdd)
            gpt_gemm<5,2><<<dim3(6, 32, 2), 128, SMEM2>>>(
                att, aprojw + (long)i * D_ * H_ * HD_, x, nullptr,
                (H_*HD_)/2, H_*HD_, H_*HD_, D_,
                (H_*HD_)/2, (H_*HD_)/2, 1, 0, 0, 1.f, 0);

            gpt_rmsnorm<<<NTOK, 256>>>(x, xn);
        }

        // h = relu(xn @ W_fc^T)^2 : [4096,768] x [3072,768]^T -> half
        gpt_gemm<2,4><<<dim3(24, 16, 1), 256, SMEM4>>>(
            xn, fcw + (long)i * 4 * D_ * D_, hbuf, nullptr,
            D_, D_, D_, 4*D_, 0, 0, 1, 0, 0, 1.f, 0);

        // x += h @ W_proj^T  (split-K=2, atomicAdd)
        gpt_gemm<5,2><<<dim3(6, 32, 2), 128, SMEM2>>>(
            hbuf, mprojw + (long)i * D_ * 4 * D_, x, nullptr,
            (4*D_)/2, 4*D_, 4*D_, D_,
            (4*D_)/2, (4*D_)/2, 1, 0, 0, 1.f, 0);

        if (i < 6) gpt_copy<<<BTD/1024, 256>>>(skips + (long)i * BTD, x);
    }

    gpt_finalnorm<<<NTOK, 256>>>(x, (float*)d_out);
}